// round 2
// baseline (speedup 1.0000x reference)
#include <cuda_runtime.h>
#include <math.h>

// ---------------- scratch ----------------
__device__ float g_bufA[800L*64*42*42];   // conv1 out
__device__ float g_bufB[800L*64*21*21];   // conv2 out
__device__ float g_bufC[800L*64*11*11];   // conv3 out
__device__ float g_bufD[800L*2304];       // conv4 out (embeddings)
__device__ float g_protos[8*5*2304];
__device__ float g_protoInv[8*5];

// ---------------- f32x2 helpers ----------------
typedef unsigned long long u64;

__device__ __forceinline__ void fma2(u64& d, u64 a, u64 b) {
    asm("fma.rn.f32x2 %0, %1, %2, %0;" : "+l"(d) : "l"(a), "l"(b));
}
__device__ __forceinline__ u64 pack2(float x, float y) {
    u64 r; asm("mov.b64 %0, {%1, %2};" : "=l"(r) : "f"(x), "f"(y)); return r;
}
__device__ __forceinline__ void unpack2(u64 v, float& x, float& y) {
    asm("mov.b64 {%0, %1}, %2;" : "=f"(x), "=f"(y) : "l"(v));
}

// ---------------- stride-2 3x3 conv + bias + relu, FFMA2 over cout pairs ----
// Block: one image n, OYT output rows, all 64 couts.
// Thread: 8 couts (4 f32x2 pairs) x TPOS strided positions.
// Weights staged transposed [c][k][cout] so a cout pair is one LDS.64.
template<int CIN, int H, int OH, int PADLOW, int OYT, int TPOS, int CK, int PTHREADS>
__global__ void __launch_bounds__(PTHREADS*8)
conv_s2_kernel(const float* __restrict__ in, const float* __restrict__ wgt,
               const float* __restrict__ bias, float* __restrict__ out)
{
    constexpr int W = H, OW = OH;
    constexpr int RP = 2*OYT + 1;
    constexpr int WP = 2*OW + 1;
    constexpr int IN_SZ = CK*RP*WP;
    constexpr int W_SZ  = CK*9*64;
    constexpr int NPOS  = OYT*OW;
    constexpr int NT    = PTHREADS*8;

    __shared__ __align__(16) float s_in[IN_SZ];
    __shared__ __align__(16) float s_w[W_SZ];

    const int n   = blockIdx.x;
    const int oy0 = blockIdx.y * OYT;
    const int tid = threadIdx.x;
    const int px  = tid % PTHREADS;
    const int cy  = tid / PTHREADS;     // cout group 0..7 -> couts cy*8 .. cy*8+7

    int  baseoff[TPOS], oyl_arr[TPOS], ox_arr[TPOS];
    bool valid[TPOS];
#pragma unroll
    for (int p = 0; p < TPOS; p++) {
        int pos = px + p*PTHREADS;               // strided -> adjacent lanes adjacent
        valid[p] = pos < NPOS;
        if (pos >= NPOS) pos = NPOS - 1;
        int oyl = pos / OW;
        int ox  = pos - oyl*OW;
        oyl_arr[p] = oyl; ox_arr[p] = ox;
        baseoff[p] = (2*oyl)*WP + 2*ox;
    }

    u64 acc[4][TPOS];                             // 4 cout pairs x TPOS positions
#pragma unroll
    for (int i = 0; i < 4; i++)
#pragma unroll
        for (int j = 0; j < TPOS; j++) acc[i][j] = 0ull;

    for (int c0 = 0; c0 < CIN; c0 += CK) {
        // stage zero-padded input tile
        for (int idx = tid; idx < IN_SZ; idx += NT) {
            int c   = idx / (RP*WP);
            int rem = idx - c*(RP*WP);
            int r   = rem / WP;
            int s   = rem - r*WP;
            int gr  = 2*oy0 + r - PADLOW;
            int gc  = s - PADLOW;
            float v = 0.f;
            if (gr >= 0 && gr < H && gc >= 0 && gc < W)
                v = in[((n*CIN + c0 + c)*H + gr)*W + gc];
            s_in[idx] = v;
        }
        // stage weight chunk, transposed: s_w[(c*9 + k)*64 + cout]
        for (int idx = tid; idx < W_SZ; idx += NT) {
            int ck   = idx / 64;         // c*9 + k
            int cout = idx - ck*64;
            int c    = ck / 9;
            int k    = ck - c*9;
            s_w[idx] = wgt[(cout*CIN + c0 + c)*9 + k];
        }
        __syncthreads();

#pragma unroll
        for (int c = 0; c < CK; c++) {
            // hold this cin's weight pairs: 4 pairs x 9 taps (LDS.64 each)
            u64 wl2[4][9];
            const float* wb = &s_w[c*9*64 + cy*8];
#pragma unroll
            for (int cop = 0; cop < 4; cop++)
#pragma unroll
                for (int k = 0; k < 9; k++)
                    wl2[cop][k] = *(const u64*)&wb[k*64 + cop*2];

#pragma unroll
            for (int p = 0; p < TPOS; p++) {
                const float* bp = &s_in[c*(RP*WP) + baseoff[p]];
                u64 xp[9];
#pragma unroll
                for (int ky = 0; ky < 3; ky++)
#pragma unroll
                    for (int kx = 0; kx < 3; kx++) {
                        float x = bp[ky*WP + kx];
                        xp[ky*3 + kx] = pack2(x, x);
                    }
#pragma unroll
                for (int cop = 0; cop < 4; cop++)
#pragma unroll
                    for (int k = 0; k < 9; k++)
                        fma2(acc[cop][p], wl2[cop][k], xp[k]);
            }
        }
        __syncthreads();
    }

    const int oy_valid = (OH - oy0 < OYT) ? (OH - oy0) : OYT;
#pragma unroll
    for (int cop = 0; cop < 4; cop++) {
        const int cout0 = cy*8 + cop*2;
        const float b0 = bias[cout0], b1 = bias[cout0 + 1];
#pragma unroll
        for (int p = 0; p < TPOS; p++) {
            if (valid[p] && oyl_arr[p] < oy_valid) {
                float v0, v1;
                unpack2(acc[cop][p], v0, v1);
                v0 += b0; v1 += b1;
                const int off = (oy0 + oyl_arr[p])*OW + ox_arr[p];
                out[((n*64 + cout0    )*OH)*OW + off] = v0 > 0.f ? v0 : 0.f;
                out[((n*64 + cout0 + 1)*OH)*OW + off] = v1 > 0.f ? v1 : 0.f;
            }
        }
    }
}

// ---------------- prototypes + inverse norms ----------------
__global__ void protos_kernel(const float* __restrict__ emb, const int* __restrict__ y,
                              float* __restrict__ protos, float* __restrict__ protoInv)
{
    const int b = blockIdx.x / 5, c = blockIdx.x % 5;
    const int tid = threadIdx.x;                   // 256
    __shared__ int sels[25];
    if (tid < 25) sels[tid] = ((y[b*25 + tid] % 5) == c) ? 1 : 0;
    __syncthreads();

    float sq = 0.f;
    for (int d = tid; d < 2304; d += 256) {
        float v = 0.f;
#pragma unroll
        for (int s = 0; s < 25; s++)
            if (sels[s]) v += emb[(b*25 + s)*2304 + d];
        v = v / 5.0f;                              // CAP = 5
        protos[(b*5 + c)*2304 + d] = v;
        sq += v*v;
    }
    __shared__ float red[256];
    red[tid] = sq; __syncthreads();
    for (int s = 128; s > 0; s >>= 1) {
        if (tid < s) red[tid] += red[tid + s];
        __syncthreads();
    }
    if (tid == 0) protoInv[b*5 + c] = 1.f / fmaxf(sqrtf(red[0]), 1e-8f);
}

// ---------------- cosine logits ----------------
__global__ void preds_kernel(const float* __restrict__ emb, const float* __restrict__ protos,
                             const float* __restrict__ protoInv, float* __restrict__ out)
{
    const int b = blockIdx.x / 75, t = blockIdx.x % 75;
    const int tid = threadIdx.x;                   // 256
    float dot[5] = {0,0,0,0,0};
    float nsq = 0.f;
    const float* e = emb + (size_t)(200 + b*75 + t)*2304;
    for (int d = tid; d < 2304; d += 256) {
        float ev = e[d];
        nsq += ev*ev;
#pragma unroll
        for (int c = 0; c < 5; c++)
            dot[c] = fmaf(ev, protos[(b*5 + c)*2304 + d], dot[c]);
    }
    __shared__ float red[256];
    __shared__ float res[6];
    for (int q = 0; q < 6; q++) {
        red[tid] = (q == 0) ? nsq : dot[q-1];
        __syncthreads();
        for (int s = 128; s > 0; s >>= 1) {
            if (tid < s) red[tid] += red[tid + s];
            __syncthreads();
        }
        if (tid == 0) res[q] = red[0];
        __syncthreads();
    }
    if (tid < 5) {
        float inv_t = 1.f / fmaxf(sqrtf(res[0]), 1e-8f);
        out[(b*75 + t)*5 + tid] = res[1 + tid] * inv_t * protoInv[b*5 + tid];
    }
}

// ---------------- launch ----------------
extern "C" void kernel_launch(void* const* d_in, const int* in_sizes, int n_in,
                              void* d_out, int out_size)
{
    const float* xs = (const float*)d_in[0];
    const float* xt = (const float*)d_in[1];
    const int*   y  = (const int*)  d_in[2];
    const float* W1 = (const float*)d_in[3];
    const float* b1 = (const float*)d_in[4];
    const float* W2 = (const float*)d_in[5];
    const float* b2 = (const float*)d_in[6];
    const float* W3 = (const float*)d_in[7];
    const float* b3 = (const float*)d_in[8];
    const float* W4 = (const float*)d_in[9];
    const float* b4 = (const float*)d_in[10];
    float* out = (float*)d_out;

    float *bufA, *bufB, *bufC, *bufD, *pr, *pi;
    cudaGetSymbolAddress((void**)&bufA, g_bufA);
    cudaGetSymbolAddress((void**)&bufB, g_bufB);
    cudaGetSymbolAddress((void**)&bufC, g_bufC);
    cudaGetSymbolAddress((void**)&bufD, g_bufD);
    cudaGetSymbolAddress((void**)&pr,   g_protos);
    cudaGetSymbolAddress((void**)&pi,   g_protoInv);

    // conv1: 3->64, 84->42, pad_low=0. OYT=3 rows, TPOS=8, 128 threads.
    conv_s2_kernel<3,84,42,0, 3,8,3, 16><<<dim3(200,14), 128>>>(xs, W1, b1, bufA);
    conv_s2_kernel<3,84,42,0, 3,8,3, 16><<<dim3(600,14), 128>>>(xt, W1, b1, bufA + (size_t)200*64*42*42);
    // conv2: 64->64, 42->21, pad_low=0. OYT=6, TPOS=8, 128 threads.
    conv_s2_kernel<64,42,21,0, 6,8,8, 16><<<dim3(800,4), 128>>>(bufA, W2, b2, bufB);
    // conv3: 64->64, 21->11, pad_low=1. OYT=11 (whole image), TPOS=8, 128 threads.
    conv_s2_kernel<64,21,11,1, 11,8,8, 16><<<dim3(800,1), 128>>>(bufB, W3, b3, bufC);
    // conv4: 64->64, 11->6, pad_low=1. OYT=6 (whole image), TPOS=4, 72 threads.
    conv_s2_kernel<64,11,6,1, 6,4,8, 9><<<dim3(800,1), 72>>>(bufC, W4, b4, bufD);
    // head
    protos_kernel<<<40, 256>>>(bufD, y, pr, pi);
    preds_kernel<<<600, 256>>>(bufD, pr, pi, out);
}

// round 3
// speedup vs baseline: 1.2227x; 1.2227x over previous
#include <cuda_runtime.h>
#include <math.h>

// ---------------- scratch ----------------
__device__ float g_bufA[800L*64*42*42];   // conv1 out
__device__ float g_bufB[800L*64*21*21];   // conv2 out
__device__ float g_bufC[800L*64*11*11];   // conv3 out
__device__ float g_bufD[800L*2304];       // conv4 out (embeddings)
__device__ float g_protos[8*5*2304];
__device__ float g_protoInv[8*5];

// ---------------- stride-2 3x3 conv + bias + relu, vectorized LDS ----------
// Block: image n, OYT output rows, all 64 couts (COG groups x CO couts).
// Thread: CO couts x 4 CONSECUTIVE x positions -> input taps via LDS.128.
// Weights staged as float4 per (cout, cin, ky): broadcast LDS.128.
template<int CIN, int H, int OH, int PADLOW, int OYT, int XT, int CK, int COG, int CO>
__global__ void __launch_bounds__(COG*OYT*XT)
conv_s2_kernel(const float* __restrict__ in, const float* __restrict__ wgt,
               const float* __restrict__ bias, float* __restrict__ out)
{
    constexpr int W = H, OW = OH;
    constexpr int RP  = 2*OYT + 1;
    constexpr int X0MAX = (XT-1)*4;
    constexpr int WPP = ((2*X0MAX + 9) + 3) & ~3;     // padded smem row pitch
    constexpr int IN_SZ = CK*RP*WPP;
    constexpr int W_SZ  = 64*CK*12;                   // float4 per (cout,c,ky)
    constexpr int PX = OYT*XT;
    constexpr int NT = COG*PX;

    __shared__ __align__(16) float s_in[IN_SZ];
    __shared__ __align__(16) float s_w[W_SZ];

    const int n   = blockIdx.x;
    const int oy0 = blockIdx.y * OYT;
    const int tid = threadIdx.x;
    const int px  = tid % PX;
    const int cy  = tid / PX;          // cout group
    const int oyl = px / XT;
    const int x0  = (px % XT) * 4;     // 16B-aligned tap base (2*x0 mult of 8)

    float acc[CO][4];
#pragma unroll
    for (int i = 0; i < CO; i++)
#pragma unroll
        for (int j = 0; j < 4; j++) acc[i][j] = 0.f;

    for (int c0 = 0; c0 < CIN; c0 += CK) {
        // ---- stage zero-padded input tile ----
        for (int idx = tid; idx < IN_SZ; idx += NT) {
            int c   = idx / (RP*WPP);
            int rem = idx - c*(RP*WPP);
            int r   = rem / WPP;
            int s   = rem - r*WPP;
            int gr  = 2*oy0 + r - PADLOW;
            int gc  = s - PADLOW;
            float v = 0.f;
            if (gr >= 0 && gr < H && gc >= 0 && gc < W)
                v = in[((n*CIN + c0 + c)*H + gr)*W + gc];
            s_in[idx] = v;
        }
        // ---- stage weights: s_w[((cout*CK + c)*3 + ky)*4 + kx], kx=3 padded 0
        for (int idx = tid; idx < W_SZ; idx += NT) {
            int cout = idx / (CK*12);
            int rem  = idx - cout*(CK*12);
            int c    = rem / 12;
            int k    = rem - c*12;
            int ky   = k >> 2, kx = k & 3;
            s_w[idx] = (kx < 3) ? wgt[(cout*CIN + c0 + c)*9 + ky*3 + kx] : 0.f;
        }
        __syncthreads();

#pragma unroll
        for (int c = 0; c < CK; c++) {
            const float* bp = &s_in[(c*RP + 2*oyl)*WPP + 2*x0];
#pragma unroll
            for (int ky = 0; ky < 3; ky++) {
                // 9 input taps covering 4 stride-2 positions: 2x LDS.128 + LDS.32
                const float* rp = bp + ky*WPP;
                float4 A = *(const float4*)rp;
                float4 Bv = *(const float4*)(rp + 4);
                float  Cc = rp[8];
                float row[9] = {A.x, A.y, A.z, A.w, Bv.x, Bv.y, Bv.z, Bv.w, Cc};
#pragma unroll
                for (int co = 0; co < CO; co++) {
                    float4 wv = *(const float4*)&s_w[(((cy*CO + co)*CK + c)*3 + ky)*4];
                    const float wl[3] = {wv.x, wv.y, wv.z};
#pragma unroll
                    for (int p = 0; p < 4; p++)
#pragma unroll
                        for (int kx = 0; kx < 3; kx++)
                            acc[co][p] = fmaf(wl[kx], row[2*p + kx], acc[co][p]);
                }
            }
        }
        __syncthreads();
    }

    // ---- epilogue ----
    const int oy = oy0 + oyl;
    if (oy < OH) {
#pragma unroll
        for (int co = 0; co < CO; co++) {
            const int cout = cy*CO + co;
            const float bb = bias[cout];
            float* op = &out[((n*64 + cout)*OH + oy)*OW];
#pragma unroll
            for (int p = 0; p < 4; p++) {
                int x = x0 + p;
                if (x < OW) {
                    float v = acc[co][p] + bb;
                    op[x] = v > 0.f ? v : 0.f;
                }
            }
        }
    }
}

// ---------------- prototypes + inverse norms ----------------
__global__ void protos_kernel(const float* __restrict__ emb, const int* __restrict__ y,
                              float* __restrict__ protos, float* __restrict__ protoInv)
{
    const int b = blockIdx.x / 5, c = blockIdx.x % 5;
    const int tid = threadIdx.x;                   // 256
    __shared__ int sels[25];
    if (tid < 25) sels[tid] = ((y[b*25 + tid] % 5) == c) ? 1 : 0;
    __syncthreads();

    float sq = 0.f;
    for (int d = tid; d < 2304; d += 256) {
        float v = 0.f;
#pragma unroll
        for (int s = 0; s < 25; s++)
            if (sels[s]) v += emb[(b*25 + s)*2304 + d];
        v = v / 5.0f;                              // CAP = 5
        protos[(b*5 + c)*2304 + d] = v;
        sq += v*v;
    }
    __shared__ float red[256];
    red[tid] = sq; __syncthreads();
    for (int s = 128; s > 0; s >>= 1) {
        if (tid < s) red[tid] += red[tid + s];
        __syncthreads();
    }
    if (tid == 0) protoInv[b*5 + c] = 1.f / fmaxf(sqrtf(red[0]), 1e-8f);
}

// ---------------- cosine logits ----------------
__global__ void preds_kernel(const float* __restrict__ emb, const float* __restrict__ protos,
                             const float* __restrict__ protoInv, float* __restrict__ out)
{
    const int b = blockIdx.x / 75, t = blockIdx.x % 75;
    const int tid = threadIdx.x;                   // 256
    float dot[5] = {0,0,0,0,0};
    float nsq = 0.f;
    const float* e = emb + (size_t)(200 + b*75 + t)*2304;
    for (int d = tid; d < 2304; d += 256) {
        float ev = e[d];
        nsq += ev*ev;
#pragma unroll
        for (int c = 0; c < 5; c++)
            dot[c] = fmaf(ev, protos[(b*5 + c)*2304 + d], dot[c]);
    }
    __shared__ float red[256];
    __shared__ float res[6];
    for (int q = 0; q < 6; q++) {
        red[tid] = (q == 0) ? nsq : dot[q-1];
        __syncthreads();
        for (int s = 128; s > 0; s >>= 1) {
            if (tid < s) red[tid] += red[tid + s];
            __syncthreads();
        }
        if (tid == 0) res[q] = red[0];
        __syncthreads();
    }
    if (tid < 5) {
        float inv_t = 1.f / fmaxf(sqrtf(res[0]), 1e-8f);
        out[(b*75 + t)*5 + tid] = res[1 + tid] * inv_t * protoInv[b*5 + tid];
    }
}

// ---------------- launch ----------------
extern "C" void kernel_launch(void* const* d_in, const int* in_sizes, int n_in,
                              void* d_out, int out_size)
{
    const float* xs = (const float*)d_in[0];
    const float* xt = (const float*)d_in[1];
    const int*   y  = (const int*)  d_in[2];
    const float* W1 = (const float*)d_in[3];
    const float* b1 = (const float*)d_in[4];
    const float* W2 = (const float*)d_in[5];
    const float* b2 = (const float*)d_in[6];
    const float* W3 = (const float*)d_in[7];
    const float* b3 = (const float*)d_in[8];
    const float* W4 = (const float*)d_in[9];
    const float* b4 = (const float*)d_in[10];
    float* out = (float*)d_out;

    float *bufA, *bufB, *bufC, *bufD, *pr, *pi;
    cudaGetSymbolAddress((void**)&bufA, g_bufA);
    cudaGetSymbolAddress((void**)&bufB, g_bufB);
    cudaGetSymbolAddress((void**)&bufC, g_bufC);
    cudaGetSymbolAddress((void**)&bufD, g_bufD);
    cudaGetSymbolAddress((void**)&pr,   g_protos);
    cudaGetSymbolAddress((void**)&pi,   g_protoInv);

    // <CIN,H,OH,PADLOW, OYT,XT,CK, COG,CO>
    // conv1: 3->64, 84->42, pad_low=0. 8 groups x 8 couts, 3 rows, XT=11. NT=264.
    conv_s2_kernel<3,84,42,0, 3,11,3, 8,8><<<dim3(200,14), 264>>>(xs, W1, b1, bufA);
    conv_s2_kernel<3,84,42,0, 3,11,3, 8,8><<<dim3(600,14), 264>>>(xt, W1, b1, bufA + (size_t)200*64*42*42);
    // conv2: 64->64, 42->21, pad_low=0. 16 groups x 4 couts, 3 rows, XT=6. NT=288.
    conv_s2_kernel<64,42,21,0, 3,6,8, 16,4><<<dim3(800,7), 288>>>(bufA, W2, b2, bufB);
    // conv3: 64->64, 21->11, pad_low=1. 6 rows, XT=3. NT=288.
    conv_s2_kernel<64,21,11,1, 6,3,8, 16,4><<<dim3(800,2), 288>>>(bufB, W3, b3, bufC);
    // conv4: 64->64, 11->6, pad_low=1. 6 rows (whole), XT=2. NT=192.
    conv_s2_kernel<64,11,6,1, 6,2,8, 16,4><<<dim3(800,1), 192>>>(bufC, W4, b4, bufD);
    // head
    protos_kernel<<<40, 256>>>(bufD, y, pr, pi);
    preds_kernel<<<600, 256>>>(bufD, pr, pi, out);
}

// round 4
// speedup vs baseline: 1.4990x; 1.2259x over previous
#include <cuda_runtime.h>
#include <math.h>

typedef unsigned long long u64;

// ---------------- scratch ----------------
__device__ float g_bufA[800L*64*42*42];   // conv1 out
__device__ float g_bufB[800L*64*21*21];   // conv2 out
__device__ float g_bufC[800L*64*11*11];   // conv3 out
__device__ float g_bufD[800L*2304];       // conv4 out (embeddings)
__device__ float g_protos[8*5*2304];
__device__ float g_protoInv[8*5];
// prepacked duplicated weights: [c][pair(32)][ky(3)][4] u64 ({w_even,w_odd}, kx3=0)
__device__ u64 g_w2_1[3*32*12];
__device__ u64 g_w2_2[64*32*12];
__device__ u64 g_w2_3[64*32*12];
__device__ u64 g_w2_4[64*32*12];

// ---------------- f32x2 helpers ----------------
__device__ __forceinline__ void fma2(u64& d, u64 a, u64 b) {
    asm("fma.rn.f32x2 %0, %1, %2, %0;" : "+l"(d) : "l"(a), "l"(b));
}
__device__ __forceinline__ u64 pack2(float x, float y) {
    u64 r; asm("mov.b64 %0, {%1, %2};" : "=l"(r) : "f"(x), "f"(y)); return r;
}
__device__ __forceinline__ void unpack2(u64 v, float& x, float& y) {
    asm("mov.b64 {%0, %1}, %2;" : "=f"(x), "=f"(y) : "l"(v));
}

// ---------------- weight prepack: OIHW -> [c][pair][ky][4] u64 ----------------
__global__ void prepack_kernel(const float* __restrict__ w, u64* __restrict__ w2, int CIN)
{
    int gid = blockIdx.x * 256 + threadIdx.x;
    int total = CIN * 32 * 12;
    if (gid >= total) return;
    int c    = gid / (32*12);
    int rem  = gid - c*(32*12);
    int pair = rem / 12;
    int k    = rem - pair*12;
    int ky   = k >> 2, kx = k & 3;
    u64 v = 0;
    if (kx < 3) {
        float w0 = w[((2*pair    )*CIN + c)*9 + ky*3 + kx];
        float w1 = w[((2*pair + 1)*CIN + c)*9 + ky*3 + kx];
        v = ((u64)__float_as_uint(w1) << 32) | (u64)__float_as_uint(w0);
    }
    w2[gid] = v;
}

// ---------------- stride-2 3x3 conv + bias + relu (FFMA2, deinterleaved) ----
// Block: image n, OYT output rows, all 64 couts (8 groups x 4 pairs).
// Thread: 4 cout-pairs x 4 consecutive x positions (one quad).
// Input smem: even/odd column planes -> conflict-free LDS.128 taps.
template<int CIN, int H, int OH, int PADLOW, int OYT, int XT, int CK>
__global__ void __launch_bounds__(8*OYT*XT)
conv_s2_kernel(const float* __restrict__ in, const u64* __restrict__ w2,
               const float* __restrict__ bias, float* __restrict__ out)
{
    constexpr int W = H, OW = OH;
    constexpr int PX   = OYT*XT;
    constexpr int NT   = 8*PX;
    constexpr int RP   = 2*OYT + 1;
    constexpr int EP   = 4*XT + 4;       // plane pitch (even/odd), mult of 4
    constexpr int ROWF = 2*EP;           // floats per (c,r) row (both planes)
    constexpr int SRAW = 8*XT + 1;       // raw columns staged
    constexpr int IN_SZ = CK*RP*ROWF;
    constexpr int W_SZ  = CK*32*12;      // u64 elements

    __shared__ __align__(16) float s_in[IN_SZ];
    __shared__ __align__(16) u64   s_w[W_SZ];

    const int n   = blockIdx.x;
    const int oy0 = blockIdx.y * OYT;
    const int tid = threadIdx.x;
    const int cy  = tid / PX;            // cout group 0..7 (couts cy*8..cy*8+7)
    const int px  = tid % PX;
    const int oyl = px / XT;
    const int x0  = (px % XT) * 4;

    u64 acc[4][4];
#pragma unroll
    for (int i = 0; i < 4; i++)
#pragma unroll
        for (int j = 0; j < 4; j++) acc[i][j] = 0ull;

    for (int c0 = 0; c0 < CIN; c0 += CK) {
        // ---- stage input tile, de-interleaved even/odd columns ----
        for (int idx = tid; idx < CK*RP*SRAW; idx += NT) {
            int c   = idx / (RP*SRAW);
            int rem = idx - c*(RP*SRAW);
            int r   = rem / SRAW;
            int s   = rem - r*SRAW;
            int gr  = 2*oy0 + r - PADLOW;
            int gc  = s - PADLOW;
            float v = 0.f;
            if (gr >= 0 && gr < H && gc >= 0 && gc < W)
                v = in[((n*CIN + c0 + c)*H + gr)*W + gc];
            s_in[(c*RP + r)*ROWF + (s & 1)*EP + (s >> 1)] = v;
        }
        // ---- stage prepacked weights: straight linear copy ----
        {
            const u64* src = w2 + c0*(32*12);
            for (int idx = tid; idx < W_SZ; idx += NT)
                s_w[idx] = src[idx];
        }
        __syncthreads();

#pragma unroll
        for (int c = 0; c < CK; c++) {
            const float* base = &s_in[(c*RP + 2*oyl)*ROWF + x0];
#pragma unroll
            for (int ky = 0; ky < 3; ky++) {
                const float* rp = base + ky*ROWF;
                float4 E = *(const float4*)rp;       // even[x0..x0+3]
                float  e4 = rp[4];                    // even[x0+4]
                float4 O = *(const float4*)(rp + EP); // odd [x0..x0+3]
                u64 xE[5], xO[4];
                xE[0] = pack2(E.x, E.x); xE[1] = pack2(E.y, E.y);
                xE[2] = pack2(E.z, E.z); xE[3] = pack2(E.w, E.w);
                xE[4] = pack2(e4, e4);
                xO[0] = pack2(O.x, O.x); xO[1] = pack2(O.y, O.y);
                xO[2] = pack2(O.z, O.z); xO[3] = pack2(O.w, O.w);
#pragma unroll
                for (int cop = 0; cop < 4; cop++) {
                    const u64* wp = &s_w[((c*32 + cy*4 + cop)*3 + ky)*4];
                    ulonglong2 wv = *(const ulonglong2*)wp;  // taps kx0,kx1
                    u64 wt2 = wp[2];                          // tap kx2
#pragma unroll
                    for (int p = 0; p < 4; p++) {
                        fma2(acc[cop][p], wv.x, xE[p]);
                        fma2(acc[cop][p], wv.y, xO[p]);
                        fma2(acc[cop][p], wt2,  xE[p+1]);
                    }
                }
            }
        }
        __syncthreads();
    }

    // ---- epilogue ----
    const int oy = oy0 + oyl;
    if (oy < OH) {
#pragma unroll
        for (int cop = 0; cop < 4; cop++) {
            const int cout0 = cy*8 + 2*cop;
            const float b0 = bias[cout0], b1 = bias[cout0 + 1];
            float* op0 = &out[((n*64 + cout0    )*OH + oy)*OW];
            float* op1 = &out[((n*64 + cout0 + 1)*OH + oy)*OW];
#pragma unroll
            for (int p = 0; p < 4; p++) {
                int x = x0 + p;
                if (x < OW) {
                    float v0, v1;
                    unpack2(acc[cop][p], v0, v1);
                    v0 += b0; v1 += b1;
                    op0[x] = v0 > 0.f ? v0 : 0.f;
                    op1[x] = v1 > 0.f ? v1 : 0.f;
                }
            }
        }
    }
}

// ---------------- prototypes + inverse norms ----------------
__global__ void protos_kernel(const float* __restrict__ emb, const int* __restrict__ y,
                              float* __restrict__ protos, float* __restrict__ protoInv)
{
    const int b = blockIdx.x / 5, c = blockIdx.x % 5;
    const int tid = threadIdx.x;                   // 256
    __shared__ int sels[25];
    if (tid < 25) sels[tid] = ((y[b*25 + tid] % 5) == c) ? 1 : 0;
    __syncthreads();

    float sq = 0.f;
    for (int d = tid; d < 2304; d += 256) {
        float v = 0.f;
#pragma unroll
        for (int s = 0; s < 25; s++)
            if (sels[s]) v += emb[(b*25 + s)*2304 + d];
        v = v / 5.0f;                              // CAP = 5
        protos[(b*5 + c)*2304 + d] = v;
        sq += v*v;
    }
    __shared__ float red[256];
    red[tid] = sq; __syncthreads();
    for (int s = 128; s > 0; s >>= 1) {
        if (tid < s) red[tid] += red[tid + s];
        __syncthreads();
    }
    if (tid == 0) protoInv[b*5 + c] = 1.f / fmaxf(sqrtf(red[0]), 1e-8f);
}

// ---------------- cosine logits ----------------
__global__ void preds_kernel(const float* __restrict__ emb, const float* __restrict__ protos,
                             const float* __restrict__ protoInv, float* __restrict__ out)
{
    const int b = blockIdx.x / 75, t = blockIdx.x % 75;
    const int tid = threadIdx.x;                   // 256
    float dot[5] = {0,0,0,0,0};
    float nsq = 0.f;
    const float* e = emb + (size_t)(200 + b*75 + t)*2304;
    for (int d = tid; d < 2304; d += 256) {
        float ev = e[d];
        nsq += ev*ev;
#pragma unroll
        for (int c = 0; c < 5; c++)
            dot[c] = fmaf(ev, protos[(b*5 + c)*2304 + d], dot[c]);
    }
    __shared__ float red[256];
    __shared__ float res[6];
    for (int q = 0; q < 6; q++) {
        red[tid] = (q == 0) ? nsq : dot[q-1];
        __syncthreads();
        for (int s = 128; s > 0; s >>= 1) {
            if (tid < s) red[tid] += red[tid + s];
            __syncthreads();
        }
        if (tid == 0) res[q] = red[0];
        __syncthreads();
    }
    if (tid < 5) {
        float inv_t = 1.f / fmaxf(sqrtf(res[0]), 1e-8f);
        out[(b*75 + t)*5 + tid] = res[1 + tid] * inv_t * protoInv[b*5 + tid];
    }
}

// ---------------- launch ----------------
extern "C" void kernel_launch(void* const* d_in, const int* in_sizes, int n_in,
                              void* d_out, int out_size)
{
    const float* xs = (const float*)d_in[0];
    const float* xt = (const float*)d_in[1];
    const int*   y  = (const int*)  d_in[2];
    const float* W1 = (const float*)d_in[3];
    const float* b1 = (const float*)d_in[4];
    const float* W2 = (const float*)d_in[5];
    const float* b2 = (const float*)d_in[6];
    const float* W3 = (const float*)d_in[7];
    const float* b3 = (const float*)d_in[8];
    const float* W4 = (const float*)d_in[9];
    const float* b4 = (const float*)d_in[10];
    float* out = (float*)d_out;

    float *bufA, *bufB, *bufC, *bufD, *pr, *pi;
    u64 *w21, *w22, *w23, *w24;
    cudaGetSymbolAddress((void**)&bufA, g_bufA);
    cudaGetSymbolAddress((void**)&bufB, g_bufB);
    cudaGetSymbolAddress((void**)&bufC, g_bufC);
    cudaGetSymbolAddress((void**)&bufD, g_bufD);
    cudaGetSymbolAddress((void**)&pr,   g_protos);
    cudaGetSymbolAddress((void**)&pi,   g_protoInv);
    cudaGetSymbolAddress((void**)&w21,  g_w2_1);
    cudaGetSymbolAddress((void**)&w22,  g_w2_2);
    cudaGetSymbolAddress((void**)&w23,  g_w2_3);
    cudaGetSymbolAddress((void**)&w24,  g_w2_4);

    // prepack weights (tiny)
    prepack_kernel<<<(3*32*12 + 255)/256, 256>>>(W1, w21, 3);
    prepack_kernel<<<(64*32*12 + 255)/256, 256>>>(W2, w22, 64);
    prepack_kernel<<<(64*32*12 + 255)/256, 256>>>(W3, w23, 64);
    prepack_kernel<<<(64*32*12 + 255)/256, 256>>>(W4, w24, 64);

    // <CIN,H,OH,PADLOW, OYT,XT,CK>
    // conv1: 3->64, 84->42. OYT=6, XT=11 (44 cols), NT=528, grid(800,7)
    conv_s2_kernel<3,84,42,0, 6,11,3><<<dim3(200,7), 528>>>(xs, w21, b1, bufA);
    conv_s2_kernel<3,84,42,0, 6,11,3><<<dim3(600,7), 528>>>(xt, w21, b1, bufA + (size_t)200*64*42*42);
    // conv2: 64->64, 42->21. OYT=6, XT=6 (24 cols), NT=288, grid(800,4)
    conv_s2_kernel<64,42,21,0, 6,6,8><<<dim3(800,4), 288>>>(bufA, w22, b2, bufB);
    // conv3: 64->64, 21->11, pad_low=1. OYT=11, XT=3 (12 cols), NT=264, grid(800,1)
    conv_s2_kernel<64,21,11,1, 11,3,8><<<dim3(800,1), 264>>>(bufB, w23, b3, bufC);
    // conv4: 64->64, 11->6, pad_low=1. OYT=6, XT=2 (8 cols), NT=96, grid(800,1)
    conv_s2_kernel<64,11,6,1, 6,2,8><<<dim3(800,1), 96>>>(bufC, w24, b4, bufD);
    // head
    protos_kernel<<<40, 256>>>(bufD, y, pr, pi);
    preds_kernel<<<600, 256>>>(bufD, pr, pi, out);
}